// round 1
// baseline (speedup 1.0000x reference)
#include <cuda_runtime.h>
#include <cuda_bf16.h>

// Shapes fixed by the problem
#define N_   8
#define C_   256
#define HW_  16384
#define S_   16

// Scratch (device globals — no allocation allowed)
__device__ float g_Srgb[N_ * S_ * C_];   // gathered sample features [n][s][c]
__device__ float g_h[N_ * S_ * C_];      // linear-layer outputs     [n][s][c]

// ---------------------------------------------------------------------------
// Prep kernel: gather S_rgb and compute h = S_rgb @ W^T + b  (tiny: 8 blocks)
// ---------------------------------------------------------------------------
__global__ __launch_bounds__(C_) void prep_kernel(
    const float* __restrict__ rgb,
    const void*  __restrict__ idx_raw,
    const float* __restrict__ W,
    const float* __restrict__ b,
    const float* __restrict__ gamma_p)
{
    if (gamma_p[0] == 0.0f) return;  // outputs unused when gamma==0 (exact algebra)

    const int n   = blockIdx.x;
    const int tid = threadIdx.x;     // 0..255, used as channel c and as out-dim d

    // Runtime detection of index dtype (int64 vs int32).
    // If stored as int32, pairing two entries as int64 almost surely leaves the
    // [0, HW) range for at least one of the 128 entries.
    const long long* p64 = (const long long*)idx_raw;
    const int*       p32 = (const int*)idx_raw;
    bool is64 = true;
    for (int i = 0; i < N_ * S_; i++) {
        long long v = p64[i];
        if (v < 0 || v >= HW_) { is64 = false; break; }
    }

    __shared__ float Srgb[S_][C_];
    const float* rgbn = rgb + (size_t)n * C_ * HW_;

    #pragma unroll
    for (int s = 0; s < S_; s++) {
        int q = is64 ? (int)p64[n * S_ + s] : p32[n * S_ + s];
        float v = rgbn[tid * HW_ + q];
        Srgb[s][tid] = v;
        g_Srgb[(n * S_ + s) * C_ + tid] = v;
    }
    __syncthreads();

    // h[s][d] = b[d] + sum_c Srgb[s][c] * W[d][c]   (thread owns d)
    const int d = tid;
    float hv[S_];
    #pragma unroll
    for (int s = 0; s < S_; s++) hv[s] = b[d];
    for (int c = 0; c < C_; c++) {
        float w = W[d * C_ + c];
        #pragma unroll
        for (int s = 0; s < S_; s++) hv[s] = fmaf(Srgb[s][c], w, hv[s]);
    }
    #pragma unroll
    for (int s = 0; s < S_; s++) g_h[(n * S_ + s) * C_ + d] = hv[s];
}

// ---------------------------------------------------------------------------
// Main kernel: grid (HW/128, N), 128 threads, each thread owns one q.
//   gamma==0  -> pure float4 relu-stream (exact: relu(id + 0*out) = relu(id))
//   gamma!=0  -> fused  out = relu(id + gamma * (x @ S_rgb^T) @ h)
// ---------------------------------------------------------------------------
__global__ __launch_bounds__(128) void main_kernel(
    const float* __restrict__ rgb,
    const float* __restrict__ gamma_p,
    float* __restrict__ out)
{
    const float gamma = gamma_p[0];

    if (gamma == 0.0f) {
        // Block-uniform fast path: elementwise relu copy, vectorized.
        size_t tid = (size_t)(blockIdx.y * gridDim.x + blockIdx.x) * blockDim.x
                   + threadIdx.x;
        size_t nthreads = (size_t)gridDim.x * gridDim.y * blockDim.x;
        const float4* in4  = (const float4*)rgb;
        float4*       out4 = (float4*)out;
        const size_t n4 = (size_t)N_ * C_ * HW_ / 4;
        for (size_t i = tid; i < n4; i += nthreads) {
            float4 v = in4[i];
            v.x = fmaxf(v.x, 0.0f);
            v.y = fmaxf(v.y, 0.0f);
            v.z = fmaxf(v.z, 0.0f);
            v.w = fmaxf(v.w, 0.0f);
            out4[i] = v;
        }
        return;
    }

    __shared__ float Ssh[S_][C_];
    __shared__ float Hsh[S_][C_];

    const int n  = blockIdx.y;
    const int t  = threadIdx.x;
    const int q  = blockIdx.x * 128 + t;

    for (int i = t; i < S_ * C_; i += 128) {
        Ssh[0][i] = g_Srgb[n * S_ * C_ + i];
        Hsh[0][i] = g_h[n * S_ * C_ + i];
    }
    __syncthreads();

    const float* rgbn = rgb + (size_t)n * C_ * HW_;
    float*       outn = out + (size_t)n * C_ * HW_;

    // Phase 1: adj[s] = sum_c x[q,c] * S_rgb[s,c]   (loads coalesced along q)
    float acc[S_];
    #pragma unroll
    for (int s = 0; s < S_; s++) acc[s] = 0.0f;
    for (int c = 0; c < C_; c++) {
        float v = rgbn[c * HW_ + q];
        #pragma unroll
        for (int s = 0; s < S_; s++) acc[s] = fmaf(v, Ssh[s][c], acc[s]);
    }

    // Phase 2: out[c] = relu(id + gamma * sum_s adj[s] * h[s,c])
    for (int c = 0; c < C_; c++) {
        float o = 0.0f;
        #pragma unroll
        for (int s = 0; s < S_; s++) o = fmaf(acc[s], Hsh[s][c], o);
        float idv = rgbn[c * HW_ + q];           // L1/L2 hit (same tile as phase 1)
        outn[c * HW_ + q] = fmaxf(fmaf(gamma, o, idv), 0.0f);
    }
}

extern "C" void kernel_launch(void* const* d_in, const int* in_sizes, int n_in,
                              void* d_out, int out_size)
{
    const float* rgb   = (const float*)d_in[0];
    const void*  idx   = d_in[1];                 // int64 or int32, detected on device
    const float* W     = (const float*)d_in[2];
    const float* b     = (const float*)d_in[3];
    const float* gamma = (const float*)d_in[4];
    float*       out   = (float*)d_out;

    prep_kernel<<<N_, C_>>>(rgb, idx, W, b, gamma);
    dim3 grid(HW_ / 128, N_);
    main_kernel<<<grid, 128>>>(rgb, gamma, out);
}

// round 4
// speedup vs baseline: 1.0784x; 1.0784x over previous
#include <cuda_runtime.h>
#include <cuda_bf16.h>

// Shapes fixed by the problem
#define N_   8
#define C_   256
#define HW_  16384
#define S_   16

// Scratch (device globals — no allocation allowed)
__device__ float g_Srgb[N_ * S_ * C_];   // gathered sample features [n][s][c]
__device__ float g_h[N_ * S_ * C_];      // linear-layer outputs     [n][s][c]

// ---------------------------------------------------------------------------
// Lean relu-stream kernel: runs ONLY when gamma == 0 (exact algebra:
// relu(id + 0*out) = relu(id)). Minimal registers -> high occupancy -> HBM cap.
// ---------------------------------------------------------------------------
__global__ __launch_bounds__(256) void relu_stream_kernel(
    const float* __restrict__ rgb,
    const float* __restrict__ gamma_p,
    float* __restrict__ out)
{
    if (gamma_p[0] != 0.0f) return;

    const float4* __restrict__ in4  = (const float4*)rgb;
    float4*       __restrict__ out4 = (float4*)out;
    const size_t n4 = (size_t)N_ * C_ * HW_ / 4;   // 8,388,608

    size_t i      = (size_t)blockIdx.x * blockDim.x + threadIdx.x;
    size_t stride = (size_t)gridDim.x * blockDim.x;
    for (; i < n4; i += stride) {
        float4 v = in4[i];
        v.x = fmaxf(v.x, 0.0f);
        v.y = fmaxf(v.y, 0.0f);
        v.z = fmaxf(v.z, 0.0f);
        v.w = fmaxf(v.w, 0.0f);
        out4[i] = v;
    }
}

// ---------------------------------------------------------------------------
// Prep kernel: gather S_rgb and compute h = S_rgb @ W^T + b  (tiny: 8 blocks)
// ---------------------------------------------------------------------------
__global__ __launch_bounds__(C_) void prep_kernel(
    const float* __restrict__ rgb,
    const void*  __restrict__ idx_raw,
    const float* __restrict__ W,
    const float* __restrict__ b,
    const float* __restrict__ gamma_p)
{
    if (gamma_p[0] == 0.0f) return;  // outputs unused when gamma==0

    const int n   = blockIdx.x;
    const int tid = threadIdx.x;     // 0..255, used as channel c and as out-dim d

    // Runtime detection of index dtype (int64 vs int32).
    // IMPORTANT: probe only the first 64 int64 words = 512 bytes, which is
    // within the buffer for EITHER dtype (int32 buffer = 512B, int64 = 1024B).
    // If data is int32, an int64 word = lo + hi*2^32 with hi in [0,16384);
    // any nonzero hi pushes v >= 2^32 >> HW_, so detection fails fast.
    // P(misdetect) = P(all 64 hi-words == 0) = (1/16384)^64 ~ 0.
    const long long* p64 = (const long long*)idx_raw;
    const int*       p32 = (const int*)idx_raw;
    bool is64 = true;
    for (int i = 0; i < 64; i++) {
        long long v = p64[i];
        if (v < 0 || v >= HW_) { is64 = false; break; }
    }

    __shared__ float Srgb[S_][C_];
    const float* rgbn = rgb + (size_t)n * C_ * HW_;

    #pragma unroll
    for (int s = 0; s < S_; s++) {
        int q = is64 ? (int)p64[n * S_ + s] : p32[n * S_ + s];
        float v = rgbn[tid * HW_ + q];
        Srgb[s][tid] = v;
        g_Srgb[(n * S_ + s) * C_ + tid] = v;
    }
    __syncthreads();

    // h[s][d] = b[d] + sum_c Srgb[s][c] * W[d][c]   (thread owns d)
    const int d = tid;
    float hv[S_];
    #pragma unroll
    for (int s = 0; s < S_; s++) hv[s] = b[d];
    for (int c = 0; c < C_; c++) {
        float w = W[d * C_ + c];
        #pragma unroll
        for (int s = 0; s < S_; s++) hv[s] = fmaf(Srgb[s][c], w, hv[s]);
    }
    #pragma unroll
    for (int s = 0; s < S_; s++) g_h[(n * S_ + s) * C_ + d] = hv[s];
}

// ---------------------------------------------------------------------------
// Fused full-path kernel: runs ONLY when gamma != 0.
// grid (HW/128, N), 128 threads, each thread owns one q.
//   out = relu(id + gamma * (x @ S_rgb^T) @ h)
// ---------------------------------------------------------------------------
__global__ __launch_bounds__(128) void fused_kernel(
    const float* __restrict__ rgb,
    const float* __restrict__ gamma_p,
    float* __restrict__ out)
{
    const float gamma = gamma_p[0];
    if (gamma == 0.0f) return;       // handled by relu_stream_kernel

    __shared__ float Ssh[S_][C_];
    __shared__ float Hsh[S_][C_];

    const int n  = blockIdx.y;
    const int t  = threadIdx.x;
    const int q  = blockIdx.x * 128 + t;

    for (int i = t; i < S_ * C_; i += 128) {
        Ssh[0][i] = g_Srgb[n * S_ * C_ + i];
        Hsh[0][i] = g_h[n * S_ * C_ + i];
    }
    __syncthreads();

    const float* rgbn = rgb + (size_t)n * C_ * HW_;
    float*       outn = out + (size_t)n * C_ * HW_;

    // Phase 1: adj[s] = sum_c x[q,c] * S_rgb[s,c]   (loads coalesced along q)
    float acc[S_];
    #pragma unroll
    for (int s = 0; s < S_; s++) acc[s] = 0.0f;
    for (int c = 0; c < C_; c++) {
        float v = rgbn[c * HW_ + q];
        #pragma unroll
        for (int s = 0; s < S_; s++) acc[s] = fmaf(v, Ssh[s][c], acc[s]);
    }

    // Phase 2: out[c] = relu(id + gamma * sum_s adj[s] * h[s,c])
    for (int c = 0; c < C_; c++) {
        float o = 0.0f;
        #pragma unroll
        for (int s = 0; s < S_; s++) o = fmaf(acc[s], Hsh[s][c], o);
        float idv = rgbn[c * HW_ + q];           // L1/L2 hit (same tile)
        outn[c * HW_ + q] = fmaxf(fmaf(gamma, o, idv), 0.0f);
    }
}

extern "C" void kernel_launch(void* const* d_in, const int* in_sizes, int n_in,
                              void* d_out, int out_size)
{
    const float* rgb   = (const float*)d_in[0];
    const void*  idx   = d_in[1];                 // int64 or int32, device-detected
    const float* W     = (const float*)d_in[2];
    const float* b     = (const float*)d_in[3];
    const float* gamma = (const float*)d_in[4];
    float*       out   = (float*)d_out;

    // gamma==0 path: lean stream kernel (others early-exit cheaply)
    relu_stream_kernel<<<2368, 256>>>(rgb, gamma, out);   // 148 SMs * 16 blocks

    // gamma!=0 path
    prep_kernel<<<N_, C_>>>(rgb, idx, W, b, gamma);
    dim3 grid(HW_ / 128, N_);
    fused_kernel<<<grid, 128>>>(rgb, gamma, out);
}